// round 15
// baseline (speedup 1.0000x reference)
#include <cuda_runtime.h>
#include <cuda_fp16.h>
#include <cstdint>

#define NB   10
#define C    64
#define HW   16384
#define KCB  512
#define NG   32
#define TOKT 128
#define THREADS 256

// ---- main-kernel smem layout (bytes from dynamic base) ----
#define WB_OFF   0                // 2 stages x (2 planes x 9216B) = 36864
#define SB_OFF   36864            // sbias 512 f32 = 2048
#define ZR_OFF   38912            // zrow 128 f32 = 512
#define WZB_OFF  39424            // wz_b 64 f32 = 256
#define SMEM_TOTAL 39680
// epilogue y-stage reuses [0 .. 33792): 64 rows x 132 f32

// ---------------- device-global scratch ----------------
__device__ float g_ps[NB * NG * 2], g_ps2[NB * NG * 2];     // GN partial sums
__device__ float g_sbias[NB * KCB];                         // incl 0.125*log2e
__device__ __align__(16) __half g_W2T[NB * KCB * C];        // [b][k][c] fp16
__device__ __align__(16) __half g_mb2[C * KCB];             // [o][k]   fp16

#define SCALE_L2E 0.18033688011112042f   // 0.125 * log2(e)

// ---------------- helpers ----------------
__device__ __forceinline__ uint32_t smem_u32(const void* p) {
    uint32_t a;
    asm("{ .reg .u64 t; cvta.to.shared.u64 t, %1; cvt.u32.u64 %0, t; }" : "=r"(a) : "l"(p));
    return a;
}
__device__ __forceinline__ void mma16816(float* c,
        uint32_t a0, uint32_t a1, uint32_t a2, uint32_t a3,
        uint32_t b0, uint32_t b1) {
    asm volatile(
        "mma.sync.aligned.m16n8k16.row.col.f32.f16.f16.f32 "
        "{%0,%1,%2,%3}, {%4,%5,%6,%7}, {%8,%9}, {%0,%1,%2,%3};"
        : "+f"(c[0]), "+f"(c[1]), "+f"(c[2]), "+f"(c[3])
        : "r"(a0), "r"(a1), "r"(a2), "r"(a3), "r"(b0), "r"(b1));
}
#define LDSM4(r, addr) \
    asm volatile("ldmatrix.sync.aligned.m8n8.x4.shared.b16 {%0,%1,%2,%3}, [%4];" \
        : "=r"((r)[0]), "=r"((r)[1]), "=r"((r)[2]), "=r"((r)[3]) : "r"(addr))
__device__ __forceinline__ float ex2f(float x) {
    float r;
    asm("ex2.approx.ftz.f32 %0, %1;" : "=f"(r) : "f"(x));
    return r;
}
__device__ __forceinline__ uint32_t packh2(float a, float b) {
    __half2 h = __floats2half2_rn(a, b);
    return *reinterpret_cast<uint32_t*>(&h);
}

// ---------------- K1: GroupNorm partial sums (2 blocks per group) ----------------
__global__ void gn_partial_kernel(const float* __restrict__ x) {
    cudaTriggerProgrammaticLaunchCompletion();   // let prep launch & stage early
    int blk = blockIdx.x;                  // 0..639 = (bg<<1)|q
    const float4* p = (const float4*)(x + (size_t)(blk >> 1) * (2 * HW) + (size_t)(blk & 1) * 16384);
    float s = 0.f, ss = 0.f;
    #pragma unroll
    for (int it = 0; it < 16; it++) {
        float4 v = p[threadIdx.x + it * 256];
        s  += (v.x + v.y) + (v.z + v.w);
        ss += (v.x * v.x + v.y * v.y) + (v.z * v.z + v.w * v.w);
    }
    #pragma unroll
    for (int o = 16; o; o >>= 1) {
        s  += __shfl_xor_sync(0xFFFFFFFFu, s, o);
        ss += __shfl_xor_sync(0xFFFFFFFFu, ss, o);
    }
    __shared__ float sm1[8], sm2[8];
    int w = threadIdx.x >> 5;
    if ((threadIdx.x & 31) == 0) { sm1[w] = s; sm2[w] = ss; }
    __syncthreads();
    if (threadIdx.x == 0) {
        float ts = 0.f, tss = 0.f;
        #pragma unroll
        for (int i = 0; i < 8; i++) { ts += sm1[i]; tss += sm2[i]; }
        g_ps[blk] = ts;
        g_ps2[blk] = tss;
    }
}

// ---------------- K2: merged weight prep (32 blocks, k-tile 16) ----------------
#define KT      16
#define MP_MT   0          // mb tile [64c][16k]        1024
#define MP_PW   1024       // phi_w   [64o][64c]        4096
#define MP_WZ   5120       // wz_w    [64o][64c]        4096
#define MP_SC2  9216       // scA     [10][64]          640
#define MP_B2   9856       // bias2   [10][64]          640
#define MP_SHB  10496      // shB     [10][64]          640
#define MP_RST  11136      // rstd    [320]
#define MP_MN   11456      // mean    [320]
#define MP_FLOATS 11776
__global__ void merged_prep_kernel(const float* __restrict__ phi_w,
                                   const float* __restrict__ phi_b,
                                   const float* __restrict__ gn_w,
                                   const float* __restrict__ gn_b,
                                   const float* __restrict__ wz_w,
                                   const float* __restrict__ mb) {
    cudaTriggerProgrammaticLaunchCompletion();   // let main launch & read x early
    extern __shared__ float P[];
    const int tid = threadIdx.x;
    const int k0 = blockIdx.x * KT;

    // ---- GN-independent staging (overlaps gn_partial via PDL) ----
    for (int i = tid; i < 64 * KT; i += 256) {
        int c = i >> 4, kj = i & (KT - 1);
        P[MP_MT + i] = mb[c * KCB + k0 + kj];
    }
    for (int i = tid; i < 4096; i += 256) {
        P[MP_PW + i] = phi_w[i];
        P[MP_WZ + i] = wz_w[i];
    }
    __syncthreads();

    // G[k0+kj][c] pre-scale work and mb2 are GN-independent too — do them now.
    // mb2[o][k0+kj] = sum_c WZ[o][c]*MT[c][kj]
    #pragma unroll 1
    for (int pass = 0; pass < 4; pass++) {
        int o  = (tid >> 4) + pass * 16;
        int kj = tid & (KT - 1);
        float a0 = 0.f, a1 = 0.f, a2 = 0.f, a3 = 0.f;
        #pragma unroll
        for (int c = 0; c < C; c += 4) {
            a0 += P[MP_WZ + o * 64 + c + 0] * P[MP_MT + (c + 0) * KT + kj];
            a1 += P[MP_WZ + o * 64 + c + 1] * P[MP_MT + (c + 1) * KT + kj];
            a2 += P[MP_WZ + o * 64 + c + 2] * P[MP_MT + (c + 2) * KT + kj];
            a3 += P[MP_WZ + o * 64 + c + 3] * P[MP_MT + (c + 3) * KT + kj];
        }
        g_mb2[o * KCB + k0 + kj] = __float2half((a0 + a1) + (a2 + a3));
    }

    // ---- wait for gn_partial results ----
    cudaGridDependencySynchronize();

    // finalize GN stats from partials
    for (int i = tid; i < NB * NG; i += 256) {
        float ts  = g_ps[i * 2] + g_ps[i * 2 + 1];
        float tss = g_ps2[i * 2] + g_ps2[i * 2 + 1];
        const float inv = 1.f / (float)(2 * HW);
        float mean = ts * inv;
        float var  = tss * inv - mean * mean;
        P[MP_MN + i]  = mean;
        P[MP_RST + i] = rsqrtf(var + 1e-6f);
    }
    __syncthreads();
    for (int i = tid; i < NB * C; i += 256) {
        int b = i >> 6, c = i & 63, g = c >> 1;
        float a = P[MP_RST + b * NG + g] * gn_w[c];
        P[MP_SC2 + i] = a;
        P[MP_SHB + i] = gn_b[c] - P[MP_MN + b * NG + g] * a;
    }
    __syncthreads();
    for (int i = tid; i < NB * C; i += 256) {
        int b = i >> 6, c = i & 63;
        float acc = phi_b[c];
        #pragma unroll
        for (int j = 0; j < C; j++) acc += P[MP_PW + c * 64 + j] * P[MP_SHB + b * 64 + j];
        P[MP_B2 + i] = acc;
    }
    __syncthreads();

    // W2T[b][k0+kj][c] = scA[b][c] * SCALE * sum_o PW[o][c]*MT[o][kj]
    #pragma unroll 1
    for (int pass = 0; pass < 4; pass++) {
        int kj = (tid >> 6) + pass * 4;
        int c  = tid & 63;
        float a0 = 0.f, a1 = 0.f, a2 = 0.f, a3 = 0.f;
        #pragma unroll
        for (int o = 0; o < C; o += 4) {
            a0 += P[MP_PW + (o + 0) * 64 + c] * P[MP_MT + (o + 0) * KT + kj];
            a1 += P[MP_PW + (o + 1) * 64 + c] * P[MP_MT + (o + 1) * KT + kj];
            a2 += P[MP_PW + (o + 2) * 64 + c] * P[MP_MT + (o + 2) * KT + kj];
            a3 += P[MP_PW + (o + 3) * 64 + c] * P[MP_MT + (o + 3) * KT + kj];
        }
        float gval = SCALE_L2E * ((a0 + a1) + (a2 + a3));
        #pragma unroll
        for (int b = 0; b < NB; b++)
            g_W2T[b * (KCB * C) + (k0 + kj) * C + c] =
                __float2half(P[MP_SC2 + b * 64 + c] * gval);
    }

    // sbias[b][k0+kj] = SCALE * sum_c B2[b][c]*MT[c][kj]
    if (tid < NB * KT) {
        int b = tid >> 4, kj = tid & (KT - 1);
        float a0 = 0.f, a1 = 0.f;
        #pragma unroll
        for (int c = 0; c < C; c += 2) {
            a0 += P[MP_B2 + b * 64 + c]     * P[MP_MT + c * KT + kj];
            a1 += P[MP_B2 + b * 64 + c + 1] * P[MP_MT + (c + 1) * KT + kj];
        }
        g_sbias[b * KCB + k0 + kj] = SCALE_L2E * (a0 + a1);
    }
}

// ---------------- weight chunk prefetch via cp.async ----------------
__device__ __forceinline__ void prefetch_chunk(int ci, int st, int b, int tid, uint32_t smb) {
    #pragma unroll
    for (int t = 0; t < 4; t++) {
        int idx = tid + t * 256;
        int plane = idx >> 9, rem = idx & 511, row = rem >> 3, seg = rem & 7;
        const __half* src;
        if (plane == 0) src = g_W2T + b * (KCB * C) + (ci * 64 + row) * 64 + seg * 8;
        else            src = g_mb2 + row * KCB + ci * 64 + seg * 8;
        uint32_t dst = smb + WB_OFF + st * 18432 + plane * 9216 + row * 144 + seg * 16;
        asm volatile("cp.async.ca.shared.global [%0], [%1], 16;" :: "r"(dst), "l"(src) : "memory");
    }
}

// ---------------- K3: main fused kernel (A-frags before grid sync) ----------
__global__ __launch_bounds__(THREADS, 2)
void fused_main_kernel(const float* __restrict__ x, float* __restrict__ out,
                       const float* __restrict__ wz_b) {
    extern __shared__ char S[];
    const int tid = threadIdx.x, wid = tid >> 5, lane = tid & 31;
    const int g = lane >> 2, tq = lane & 3;
    const int b = blockIdx.y;
    const int tok0 = blockIdx.x * TOKT;
    const int wtok = wid * 16;
    const uint32_t smb = smem_u32(S);

    // ---- A fragments (fp16) from global x — independent of prep outputs ----
    const float* xg = x + (size_t)b * C * HW + tok0;
    uint32_t ah[4][4];
    {
        const int row0 = wtok + g, row1 = row0 + 8;
        #pragma unroll
        for (int kt = 0; kt < 4; kt++) {
            #pragma unroll
            for (int half = 0; half < 2; half++) {
                int c0 = kt * 16 + tq * 2 + half * 8;
                float v00 = xg[(size_t)c0 * HW + row0];
                float v01 = xg[(size_t)(c0 + 1) * HW + row0];
                float v10 = xg[(size_t)c0 * HW + row1];
                float v11 = xg[(size_t)(c0 + 1) * HW + row1];
                ah[kt][half * 2]     = packh2(v00, v01);
                ah[kt][half * 2 + 1] = packh2(v10, v11);
            }
        }
    }

    // ---- wait for merged_prep results, then start weight pipeline ----
    cudaGridDependencySynchronize();

    prefetch_chunk(0, 0, b, tid, smb);
    asm volatile("cp.async.commit_group;" ::: "memory");
    prefetch_chunk(1, 1, b, tid, smb);
    asm volatile("cp.async.commit_group;" ::: "memory");

    if (tid < C) ((float*)(S + WZB_OFF))[tid] = wz_b[tid];
    for (int i = tid; i < KCB; i += THREADS)
        ((float*)(S + SB_OFF))[i] = g_sbias[b * KCB + i];

    float yacc[8][4];
    #pragma unroll
    for (int nt = 0; nt < 8; nt++)
        #pragma unroll
        for (int q = 0; q < 4; q++) yacc[nt][q] = 0.f;
    float zacc[2] = {0.f, 0.f};

    const uint32_t brow = (uint32_t)(lane & 7) * 144 + (uint32_t)((lane >> 3) * 16);

    for (int ci = 0; ci < 8; ci++) {
        if (ci < 7) asm volatile("cp.async.wait_group 1;" ::: "memory");
        else        asm volatile("cp.async.wait_group 0;" ::: "memory");
        __syncthreads();

        const uint32_t stg = smb + WB_OFF + (uint32_t)((ci & 1) * 18432);
        const uint32_t Wh = stg, Mh = stg + 9216;
        const float* sbp = (const float*)(S + SB_OFF) + ci * 64;

        // ---- GEMM2 + fused exp (split accumulator chains) ----
        uint32_t eh[8], eh2[8];
        #pragma unroll
        for (int nt = 0; nt < 8; nt++) {
            uint32_t radr = (uint32_t)(nt * 8) * 144 + brow;
            uint32_t bh[8];
            LDSM4(bh,     Wh + radr);
            LDSM4(bh + 4, Wh + radr + 64);
            float sa[4] = {0.f, 0.f, 0.f, 0.f};
            float sb[4] = {0.f, 0.f, 0.f, 0.f};
            mma16816(sa, ah[0][0], ah[0][1], ah[0][2], ah[0][3], bh[0], bh[1]);
            mma16816(sb, ah[1][0], ah[1][1], ah[1][2], ah[1][3], bh[2], bh[3]);
            mma16816(sa, ah[2][0], ah[2][1], ah[2][2], ah[2][3], bh[4], bh[5]);
            mma16816(sb, ah[3][0], ah[3][1], ah[3][2], ah[3][3], bh[6], bh[7]);
            float sbx = sbp[nt * 8 + 2 * tq];
            float sby = sbp[nt * 8 + 2 * tq + 1];
            float e0 = ex2f(sa[0] + sb[0] + sbx);
            float e1 = ex2f(sa[1] + sb[1] + sby);
            float e2 = ex2f(sa[2] + sb[2] + sbx);
            float e3 = ex2f(sa[3] + sb[3] + sby);
            zacc[0] += e0 + e1;
            zacc[1] += e2 + e3;
            eh[nt]  = packh2(e0, e1);
            eh2[nt] = packh2(e2, e3);
        }

        // ---- GEMM3: y += E @ mb2^T ----
        #pragma unroll
        for (int nt = 0; nt < 8; nt++) {
            uint32_t radr = (uint32_t)(nt * 8) * 144 + brow;
            uint32_t mh[8];
            LDSM4(mh,     Mh + radr);
            LDSM4(mh + 4, Mh + radr + 64);
            #pragma unroll
            for (int kt = 0; kt < 4; kt++) {
                mma16816(yacc[nt], eh[2 * kt], eh2[2 * kt], eh[2 * kt + 1], eh2[2 * kt + 1],
                         mh[2 * kt], mh[2 * kt + 1]);
            }
        }

        __syncthreads();
        if (ci + 2 < 8) {
            prefetch_chunk(ci + 2, ci & 1, b, tid, smb);
            asm volatile("cp.async.commit_group;" ::: "memory");
        }
    }

    // Z: quad-reduce over tq lanes
    #pragma unroll
    for (int q = 0; q < 2; q++) {
        zacc[q] += __shfl_xor_sync(0xFFFFFFFFu, zacc[q], 1);
        zacc[q] += __shfl_xor_sync(0xFFFFFFFFu, zacc[q], 2);
    }
    float iz0 = 1.f / zacc[0];
    float iz1 = 1.f / zacc[1];

    // stage y to smem [o][tok] (pad 132) for coalesced output
    float* YS = (float*)S;
    __syncthreads();
    {
        int r0 = wtok + g;
        #pragma unroll
        for (int nt = 0; nt < 8; nt++) {
            int o0 = nt * 8 + 2 * tq;
            YS[o0 * 132 + r0]           = yacc[nt][0] * iz0;
            YS[(o0 + 1) * 132 + r0]     = yacc[nt][1] * iz0;
            YS[o0 * 132 + r0 + 8]       = yacc[nt][2] * iz1;
            YS[(o0 + 1) * 132 + r0 + 8] = yacc[nt][3] * iz1;
        }
    }
    __syncthreads();

    // out = y + wz_b + residual, coalesced float4
    const float* wzp = (const float*)(S + WZB_OFF);
    float* og = out + (size_t)b * C * HW + tok0;
    #pragma unroll
    for (int it = 0; it < 8; it++) {
        int i = tid + it * 256;
        int o = i >> 5, t32 = i & 31;
        float4 ys = *(const float4*)(YS + o * 132 + t32 * 4);
        float4 xr = *(const float4*)(xg + (size_t)o * HW + t32 * 4);
        float wb = wzp[o];
        float4 r;
        r.x = ys.x + xr.x + wb;
        r.y = ys.y + xr.y + wb;
        r.z = ys.z + xr.z + wb;
        r.w = ys.w + xr.w + wb;
        *(float4*)(og + (size_t)o * HW + t32 * 4) = r;
    }
}

// ---------------------------------------------------------------------------
extern "C" void kernel_launch(void* const* d_in, const int* in_sizes, int n_in,
                              void* d_out, int out_size) {
    const float* x     = (const float*)d_in[0];
    const float* mb    = (const float*)d_in[1];
    const float* phi_w = (const float*)d_in[2];
    const float* phi_b = (const float*)d_in[3];
    const float* gn_w  = (const float*)d_in[4];
    const float* gn_b  = (const float*)d_in[5];
    const float* wz_w  = (const float*)d_in[6];
    const float* wz_b  = (const float*)d_in[7];
    float* out = (float*)d_out;

    cudaFuncSetAttribute(fused_main_kernel,
                         cudaFuncAttributeMaxDynamicSharedMemorySize, SMEM_TOTAL);
    cudaFuncSetAttribute(merged_prep_kernel,
                         cudaFuncAttributeMaxDynamicSharedMemorySize, MP_FLOATS * 4);

    gn_partial_kernel<<<NB * NG * 2, 256>>>(x);

    cudaLaunchAttribute pdl[1];
    pdl[0].id = cudaLaunchAttributeProgrammaticStreamSerialization;
    pdl[0].val.programmaticStreamSerializationAllowed = 1;

    {
        cudaLaunchConfig_t cfg = {};
        cfg.gridDim = dim3(KCB / KT, 1, 1);
        cfg.blockDim = dim3(256, 1, 1);
        cfg.dynamicSmemBytes = MP_FLOATS * 4;
        cfg.stream = 0;
        cfg.attrs = pdl;
        cfg.numAttrs = 1;
        cudaLaunchKernelEx(&cfg, merged_prep_kernel, phi_w, phi_b, gn_w, gn_b, wz_w, mb);
    }
    {
        cudaLaunchConfig_t cfg = {};
        cfg.gridDim = dim3(HW / TOKT, NB, 1);
        cfg.blockDim = dim3(THREADS, 1, 1);
        cfg.dynamicSmemBytes = SMEM_TOTAL;
        cfg.stream = 0;
        cfg.attrs = pdl;
        cfg.numAttrs = 1;
        cudaLaunchKernelEx(&cfg, fused_main_kernel, x, out, wz_b);
    }
}

// round 16
// speedup vs baseline: 1.0604x; 1.0604x over previous
#include <cuda_runtime.h>
#include <cuda_fp16.h>
#include <cstdint>

#define NB   10
#define C    64
#define HW   16384
#define KCB  512
#define NG   32
#define TOKT 128
#define THREADS 256

// ---- main-kernel smem layout (bytes from dynamic base) ----
#define WB_OFF   0                // 2 stages x (2 planes x 9216B) = 36864
#define SB_OFF   36864            // sbias 512 f32 = 2048
#define ZR_OFF   38912            // zrow 128 f32 = 512
#define WZB_OFF  39424            // wz_b 64 f32 = 256
#define SMEM_TOTAL 39680
// epilogue y-stage reuses [0 .. 33792): 64 rows x 132 f32

// ---------------- device-global scratch ----------------
__device__ float g_ps[NB * NG * 2], g_ps2[NB * NG * 2];     // GN partial sums
__device__ float g_sbias[NB * KCB];                         // incl 0.125*log2e
__device__ __align__(16) __half g_W2T[NB * KCB * C];        // [b][k][c] fp16
__device__ __align__(16) __half g_mb2[C * KCB];             // [o][k]   fp16

#define SCALE_L2E 0.18033688011112042f   // 0.125 * log2(e)

// ---------------- helpers ----------------
__device__ __forceinline__ uint32_t smem_u32(const void* p) {
    uint32_t a;
    asm("{ .reg .u64 t; cvta.to.shared.u64 t, %1; cvt.u32.u64 %0, t; }" : "=r"(a) : "l"(p));
    return a;
}
__device__ __forceinline__ void mma16816(float* c,
        uint32_t a0, uint32_t a1, uint32_t a2, uint32_t a3,
        uint32_t b0, uint32_t b1) {
    asm volatile(
        "mma.sync.aligned.m16n8k16.row.col.f32.f16.f16.f32 "
        "{%0,%1,%2,%3}, {%4,%5,%6,%7}, {%8,%9}, {%0,%1,%2,%3};"
        : "+f"(c[0]), "+f"(c[1]), "+f"(c[2]), "+f"(c[3])
        : "r"(a0), "r"(a1), "r"(a2), "r"(a3), "r"(b0), "r"(b1));
}
#define LDSM4(r, addr) \
    asm volatile("ldmatrix.sync.aligned.m8n8.x4.shared.b16 {%0,%1,%2,%3}, [%4];" \
        : "=r"((r)[0]), "=r"((r)[1]), "=r"((r)[2]), "=r"((r)[3]) : "r"(addr))
__device__ __forceinline__ float ex2f(float x) {
    float r;
    asm("ex2.approx.ftz.f32 %0, %1;" : "=f"(r) : "f"(x));
    return r;
}
__device__ __forceinline__ uint32_t packh2(float a, float b) {
    __half2 h = __floats2half2_rn(a, b);
    return *reinterpret_cast<uint32_t*>(&h);
}

// ---------------- K1: GroupNorm partial sums (2 blocks/group, 512 thr) --------
__global__ void gn_partial_kernel(const float* __restrict__ x) {
    int blk = blockIdx.x;                  // 0..639 = (bg<<1)|q
    const float4* p = (const float4*)(x + (size_t)(blk >> 1) * (2 * HW) + (size_t)(blk & 1) * 16384);
    float s = 0.f, ss = 0.f;
    #pragma unroll
    for (int it = 0; it < 8; it++) {
        float4 v = p[threadIdx.x + it * 512];
        s  += (v.x + v.y) + (v.z + v.w);
        ss += (v.x * v.x + v.y * v.y) + (v.z * v.z + v.w * v.w);
    }
    #pragma unroll
    for (int o = 16; o; o >>= 1) {
        s  += __shfl_xor_sync(0xFFFFFFFFu, s, o);
        ss += __shfl_xor_sync(0xFFFFFFFFu, ss, o);
    }
    __shared__ float sm1[16], sm2[16];
    int w = threadIdx.x >> 5;
    if ((threadIdx.x & 31) == 0) { sm1[w] = s; sm2[w] = ss; }
    __syncthreads();
    if (threadIdx.x == 0) {
        float ts = 0.f, tss = 0.f;
        #pragma unroll
        for (int i = 0; i < 16; i++) { ts += sm1[i]; tss += sm2[i]; }
        g_ps[blk] = ts;
        g_ps2[blk] = tss;
    }
}

// ---------------- K2: merged weight prep (32 blocks, k-tile 16) ----------------
#define KT      16
#define MP_MT   0          // mb tile [64c][16k]        1024
#define MP_PW   1024       // phi_w   [64o][64c]        4096
#define MP_WZ   5120       // wz_w    [64o][64c]        4096
#define MP_SC2  9216       // scA     [10][64]          640
#define MP_B2   9856       // bias2   [10][64]          640
#define MP_SHB  10496      // shB     [10][64]          640
#define MP_RST  11136      // rstd    [320]
#define MP_MN   11456      // mean    [320]
#define MP_FLOATS 11776
__global__ void merged_prep_kernel(const float* __restrict__ phi_w,
                                   const float* __restrict__ phi_b,
                                   const float* __restrict__ gn_w,
                                   const float* __restrict__ gn_b,
                                   const float* __restrict__ wz_w,
                                   const float* __restrict__ mb) {
    extern __shared__ float P[];
    const int tid = threadIdx.x;
    const int k0 = blockIdx.x * KT;

    for (int i = tid; i < 64 * KT; i += 256) {
        int c = i >> 4, kj = i & (KT - 1);
        P[MP_MT + i] = mb[c * KCB + k0 + kj];
    }
    for (int i = tid; i < 4096; i += 256) {
        P[MP_PW + i] = phi_w[i];
        P[MP_WZ + i] = wz_w[i];
    }
    // finalize GN stats from partials
    for (int i = tid; i < NB * NG; i += 256) {
        float ts  = g_ps[i * 2] + g_ps[i * 2 + 1];
        float tss = g_ps2[i * 2] + g_ps2[i * 2 + 1];
        const float inv = 1.f / (float)(2 * HW);
        float mean = ts * inv;
        float var  = tss * inv - mean * mean;
        P[MP_MN + i]  = mean;
        P[MP_RST + i] = rsqrtf(var + 1e-6f);
    }
    __syncthreads();
    for (int i = tid; i < NB * C; i += 256) {
        int b = i >> 6, c = i & 63, g = c >> 1;
        float a = P[MP_RST + b * NG + g] * gn_w[c];
        P[MP_SC2 + i] = a;
        P[MP_SHB + i] = gn_b[c] - P[MP_MN + b * NG + g] * a;
    }
    __syncthreads();
    for (int i = tid; i < NB * C; i += 256) {
        int b = i >> 6, c = i & 63;
        float acc = phi_b[c];
        #pragma unroll
        for (int j = 0; j < C; j++) acc += P[MP_PW + c * 64 + j] * P[MP_SHB + b * 64 + j];
        P[MP_B2 + i] = acc;
    }
    __syncthreads();

    // W2T[b][k0+kj][c] = scA[b][c] * SCALE * sum_o PW[o][c]*MT[o][kj]
    #pragma unroll 1
    for (int pass = 0; pass < 4; pass++) {
        int kj = (tid >> 6) + pass * 4;
        int c  = tid & 63;
        float a0 = 0.f, a1 = 0.f, a2 = 0.f, a3 = 0.f;
        #pragma unroll
        for (int o = 0; o < C; o += 4) {
            a0 += P[MP_PW + (o + 0) * 64 + c] * P[MP_MT + (o + 0) * KT + kj];
            a1 += P[MP_PW + (o + 1) * 64 + c] * P[MP_MT + (o + 1) * KT + kj];
            a2 += P[MP_PW + (o + 2) * 64 + c] * P[MP_MT + (o + 2) * KT + kj];
            a3 += P[MP_PW + (o + 3) * 64 + c] * P[MP_MT + (o + 3) * KT + kj];
        }
        float gval = SCALE_L2E * ((a0 + a1) + (a2 + a3));
        #pragma unroll
        for (int b = 0; b < NB; b++)
            g_W2T[b * (KCB * C) + (k0 + kj) * C + c] =
                __float2half(P[MP_SC2 + b * 64 + c] * gval);
    }

    // mb2[o][k0+kj] = sum_c WZ[o][c]*MT[c][kj]
    #pragma unroll 1
    for (int pass = 0; pass < 4; pass++) {
        int o  = (tid >> 4) + pass * 16;
        int kj = tid & (KT - 1);
        float a0 = 0.f, a1 = 0.f, a2 = 0.f, a3 = 0.f;
        #pragma unroll
        for (int c = 0; c < C; c += 4) {
            a0 += P[MP_WZ + o * 64 + c + 0] * P[MP_MT + (c + 0) * KT + kj];
            a1 += P[MP_WZ + o * 64 + c + 1] * P[MP_MT + (c + 1) * KT + kj];
            a2 += P[MP_WZ + o * 64 + c + 2] * P[MP_MT + (c + 2) * KT + kj];
            a3 += P[MP_WZ + o * 64 + c + 3] * P[MP_MT + (c + 3) * KT + kj];
        }
        g_mb2[o * KCB + k0 + kj] = __float2half((a0 + a1) + (a2 + a3));
    }

    // sbias[b][k0+kj] = SCALE * sum_c B2[b][c]*MT[c][kj]
    if (tid < NB * KT) {
        int b = tid >> 4, kj = tid & (KT - 1);
        float a0 = 0.f, a1 = 0.f;
        #pragma unroll
        for (int c = 0; c < C; c += 2) {
            a0 += P[MP_B2 + b * 64 + c]     * P[MP_MT + c * KT + kj];
            a1 += P[MP_B2 + b * 64 + c + 1] * P[MP_MT + (c + 1) * KT + kj];
        }
        g_sbias[b * KCB + k0 + kj] = SCALE_L2E * (a0 + a1);
    }
}

// ---------------- weight chunk prefetch via cp.async ----------------
__device__ __forceinline__ void prefetch_chunk(int ci, int st, int b, int tid, uint32_t smb) {
    #pragma unroll
    for (int t = 0; t < 4; t++) {
        int idx = tid + t * 256;
        int plane = idx >> 9, rem = idx & 511, row = rem >> 3, seg = rem & 7;
        const __half* src;
        if (plane == 0) src = g_W2T + b * (KCB * C) + (ci * 64 + row) * 64 + seg * 8;
        else            src = g_mb2 + row * KCB + ci * 64 + seg * 8;
        uint32_t dst = smb + WB_OFF + st * 18432 + plane * 9216 + row * 144 + seg * 16;
        asm volatile("cp.async.ca.shared.global [%0], [%1], 16;" :: "r"(dst), "l"(src) : "memory");
    }
}

// ---------------- K3: main fused kernel (16 tok/warp, split sc chains) --------
__global__ __launch_bounds__(THREADS, 2)
void fused_main_kernel(const float* __restrict__ x, float* __restrict__ out,
                       const float* __restrict__ wz_b) {
    extern __shared__ char S[];
    const int tid = threadIdx.x, wid = tid >> 5, lane = tid & 31;
    const int g = lane >> 2, tq = lane & 3;
    const int b = blockIdx.y;
    const int tok0 = blockIdx.x * TOKT;
    const int wtok = wid * 16;
    const uint32_t smb = smem_u32(S);

    prefetch_chunk(0, 0, b, tid, smb);
    asm volatile("cp.async.commit_group;" ::: "memory");
    prefetch_chunk(1, 1, b, tid, smb);
    asm volatile("cp.async.commit_group;" ::: "memory");

    if (tid < C) ((float*)(S + WZB_OFF))[tid] = wz_b[tid];
    for (int i = tid; i < KCB; i += THREADS)
        ((float*)(S + SB_OFF))[i] = g_sbias[b * KCB + i];

    // ---- A fragments (fp16) built directly from global x ----
    const float* xg = x + (size_t)b * C * HW + tok0;
    uint32_t ah[4][4];
    {
        const int row0 = wtok + g, row1 = row0 + 8;
        #pragma unroll
        for (int kt = 0; kt < 4; kt++) {
            #pragma unroll
            for (int half = 0; half < 2; half++) {
                int c0 = kt * 16 + tq * 2 + half * 8;
                float v00 = xg[(size_t)c0 * HW + row0];
                float v01 = xg[(size_t)(c0 + 1) * HW + row0];
                float v10 = xg[(size_t)c0 * HW + row1];
                float v11 = xg[(size_t)(c0 + 1) * HW + row1];
                ah[kt][half * 2]     = packh2(v00, v01);
                ah[kt][half * 2 + 1] = packh2(v10, v11);
            }
        }
    }

    float yacc[8][4];
    #pragma unroll
    for (int nt = 0; nt < 8; nt++)
        #pragma unroll
        for (int q = 0; q < 4; q++) yacc[nt][q] = 0.f;
    float zacc[2] = {0.f, 0.f};

    const uint32_t brow = (uint32_t)(lane & 7) * 144 + (uint32_t)((lane >> 3) * 16);

    for (int ci = 0; ci < 8; ci++) {
        if (ci < 7) asm volatile("cp.async.wait_group 1;" ::: "memory");
        else        asm volatile("cp.async.wait_group 0;" ::: "memory");
        __syncthreads();

        const uint32_t stg = smb + WB_OFF + (uint32_t)((ci & 1) * 18432);
        const uint32_t Wh = stg, Mh = stg + 9216;
        const float* sbp = (const float*)(S + SB_OFF) + ci * 64;

        // ---- GEMM2 + fused exp (split accumulator chains) ----
        uint32_t eh[8], eh2[8];
        #pragma unroll
        for (int nt = 0; nt < 8; nt++) {
            uint32_t radr = (uint32_t)(nt * 8) * 144 + brow;
            uint32_t bh[8];
            LDSM4(bh,     Wh + radr);
            LDSM4(bh + 4, Wh + radr + 64);
            float sa[4] = {0.f, 0.f, 0.f, 0.f};
            float sb[4] = {0.f, 0.f, 0.f, 0.f};
            mma16816(sa, ah[0][0], ah[0][1], ah[0][2], ah[0][3], bh[0], bh[1]);
            mma16816(sb, ah[1][0], ah[1][1], ah[1][2], ah[1][3], bh[2], bh[3]);
            mma16816(sa, ah[2][0], ah[2][1], ah[2][2], ah[2][3], bh[4], bh[5]);
            mma16816(sb, ah[3][0], ah[3][1], ah[3][2], ah[3][3], bh[6], bh[7]);
            float sbx = sbp[nt * 8 + 2 * tq];
            float sby = sbp[nt * 8 + 2 * tq + 1];
            float e0 = ex2f(sa[0] + sb[0] + sbx);
            float e1 = ex2f(sa[1] + sb[1] + sby);
            float e2 = ex2f(sa[2] + sb[2] + sbx);
            float e3 = ex2f(sa[3] + sb[3] + sby);
            zacc[0] += e0 + e1;
            zacc[1] += e2 + e3;
            eh[nt]  = packh2(e0, e1);
            eh2[nt] = packh2(e2, e3);
        }

        // ---- GEMM3: y += E @ mb2^T ----
        #pragma unroll
        for (int nt = 0; nt < 8; nt++) {
            uint32_t radr = (uint32_t)(nt * 8) * 144 + brow;
            uint32_t mh[8];
            LDSM4(mh,     Mh + radr);
            LDSM4(mh + 4, Mh + radr + 64);
            #pragma unroll
            for (int kt = 0; kt < 4; kt++) {
                mma16816(yacc[nt], eh[2 * kt], eh2[2 * kt], eh[2 * kt + 1], eh2[2 * kt + 1],
                         mh[2 * kt], mh[2 * kt + 1]);
            }
        }

        __syncthreads();
        if (ci + 2 < 8) {
            prefetch_chunk(ci + 2, ci & 1, b, tid, smb);
            asm volatile("cp.async.commit_group;" ::: "memory");
        }
    }

    // row-sum Z over quad lanes
    #pragma unroll
    for (int q = 0; q < 2; q++) {
        zacc[q] += __shfl_xor_sync(0xFFFFFFFFu, zacc[q], 1);
        zacc[q] += __shfl_xor_sync(0xFFFFFFFFu, zacc[q], 2);
    }
    float* ZRp = (float*)(S + ZR_OFF);
    if (tq == 0) {
        ZRp[wtok + g]     = zacc[0];
        ZRp[wtok + 8 + g] = zacc[1];
    }
    __syncwarp();
    float iz0 = 1.f / ZRp[wtok + g];
    float iz1 = 1.f / ZRp[wtok + 8 + g];

    // stage y to smem [o][tok] (pad 132) for coalesced output
    float* YS = (float*)S;
    __syncthreads();
    {
        int r0 = wtok + g;
        #pragma unroll
        for (int nt = 0; nt < 8; nt++) {
            int o0 = nt * 8 + 2 * tq;
            YS[o0 * 132 + r0]           = yacc[nt][0] * iz0;
            YS[(o0 + 1) * 132 + r0]     = yacc[nt][1] * iz0;
            YS[o0 * 132 + r0 + 8]       = yacc[nt][2] * iz1;
            YS[(o0 + 1) * 132 + r0 + 8] = yacc[nt][3] * iz1;
        }
    }
    __syncthreads();

    // out = y + wz_b + residual, coalesced float4
    const float* wzp = (const float*)(S + WZB_OFF);
    float* og = out + (size_t)b * C * HW + tok0;
    #pragma unroll
    for (int it = 0; it < 8; it++) {
        int i = tid + it * 256;
        int o = i >> 5, t32 = i & 31;
        float4 ys = *(const float4*)(YS + o * 132 + t32 * 4);
        float4 xr = *(const float4*)(xg + (size_t)o * HW + t32 * 4);
        float wb = wzp[o];
        float4 r;
        r.x = ys.x + xr.x + wb;
        r.y = ys.y + xr.y + wb;
        r.z = ys.z + xr.z + wb;
        r.w = ys.w + xr.w + wb;
        *(float4*)(og + (size_t)o * HW + t32 * 4) = r;
    }
}

// ---------------------------------------------------------------------------
extern "C" void kernel_launch(void* const* d_in, const int* in_sizes, int n_in,
                              void* d_out, int out_size) {
    const float* x     = (const float*)d_in[0];
    const float* mb    = (const float*)d_in[1];
    const float* phi_w = (const float*)d_in[2];
    const float* phi_b = (const float*)d_in[3];
    const float* gn_w  = (const float*)d_in[4];
    const float* gn_b  = (const float*)d_in[5];
    const float* wz_w  = (const float*)d_in[6];
    const float* wz_b  = (const float*)d_in[7];
    float* out = (float*)d_out;

    cudaFuncSetAttribute(fused_main_kernel,
                         cudaFuncAttributeMaxDynamicSharedMemorySize, SMEM_TOTAL);
    cudaFuncSetAttribute(merged_prep_kernel,
                         cudaFuncAttributeMaxDynamicSharedMemorySize, MP_FLOATS * 4);

    gn_partial_kernel<<<NB * NG * 2, 512>>>(x);
    merged_prep_kernel<<<KCB / KT, 256, MP_FLOATS * 4>>>(phi_w, phi_b, gn_w, gn_b, wz_w, mb);

    dim3 grid(HW / TOKT, NB);
    fused_main_kernel<<<grid, THREADS, SMEM_TOTAL>>>(x, out, wz_b);
}